// round 2
// baseline (speedup 1.0000x reference)
#include <cuda_runtime.h>
#include <math.h>

// Problem constants (shapes fixed by the reference: (32,32,64,64), KERN=2)
#define Cc   32
#define Hh   64
#define Ww   64
#define Bn   32
#define PHh  32
#define PWw  32
#define NP   (Cc*PHh*PWw)     /* 32768 pooled points */
#define TX   64
#define TY   4
#define BPT  (Bn/TY)          /* 8 batches per thread */
#define NBLK (NP/TX)          /* 512 blocks */
#define BSTRIDE (Cc*Hh*Ww)    /* 131072 floats per batch */

// Scratch for deterministic two-stage reduction (no allocation allowed).
__device__ double g_partials[NBLK];

__global__ __launch_bounds__(TX*TY) void gkl_main_kernel(
    const float* __restrict__ mu_a, const float* __restrict__ lv_a,
    const float* __restrict__ mu_b, const float* __restrict__ lv_b)
{
    __shared__ float  sred[TY][TX][10];
    __shared__ double scon[TX];

    const int x = threadIdx.x;      // pooled-point lane (64 consecutive points)
    const int y = threadIdx.y;      // batch quarter
    const int p = blockIdx.x * TX + x;
    const int pw = p & (PWw - 1);
    const int ph = (p >> 5) & (PHh - 1);
    const int c  = p >> 10;
    // offset of top-left of the 2x2 pool window for batch (y*BPT)
    int base = (c * Hh + 2 * ph) * Ww + 2 * pw + y * BPT * BSTRIDE;

    // 10 running sums over this thread's 8 batches
    float S1 = 0.f, S2 = 0.f;
    float A0 = 0.f, A1 = 0.f, A2 = 0.f, AL = 0.f;
    float B0 = 0.f, B1 = 0.f, B2 = 0.f, BL = 0.f;

    const float INV_S2PI = 0.3989422804014327f;  // 1/sqrt(2*pi)

#pragma unroll
    for (int k = 0; k < BPT; ++k) {
        const int off = base + k * BSTRIDE;
        const float2 ma0 = *(const float2*)(mu_a + off);
        const float2 ma1 = *(const float2*)(mu_a + off + Ww);
        const float2 la0 = *(const float2*)(lv_a + off);
        const float2 la1 = *(const float2*)(lv_a + off + Ww);
        const float2 mb0 = *(const float2*)(mu_b + off);
        const float2 mb1 = *(const float2*)(mu_b + off + Ww);
        const float2 lb0 = *(const float2*)(lv_b + off);
        const float2 lb1 = *(const float2*)(lv_b + off + Ww);

        // pooled mean (avg of 4) and pooled variance (avgpool(exp)/4 = sum/16)
        const float ma = 0.25f  * (ma0.x + ma0.y + ma1.x + ma1.y);
        const float mb = 0.25f  * (mb0.x + mb0.y + mb1.x + mb1.y);
        const float va = 0.0625f * (__expf(la0.x) + __expf(la0.y) +
                                    __expf(la1.x) + __expf(la1.y));
        const float vb = 0.0625f * (__expf(lb0.x) + __expf(lb0.y) +
                                    __expf(lb1.x) + __expf(lb1.y));

        // i-side sums (distribution a only)
        S1 += ma;
        S2 += fmaf(va, va, ma * ma);

        // j-side sums
        const float iva  = __fdividef(1.0f, va);
        const float ivb  = __fdividef(1.0f, vb);
        AL += __logf(fmaf(iva, INV_S2PI, 1e-6f));
        BL += __logf(fmaf(ivb, INV_S2PI, 1e-6f));
        const float iva2 = iva * iva;
        const float ivb2 = ivb * ivb;
        A0 += iva2;               B0 += ivb2;
        A1 += ma * iva2;          B1 += mb * ivb2;
        A2 += ma * ma * iva2;     B2 += mb * mb * ivb2;
    }

    // Combine batch quarters (all 10 sums are plain additive over batch).
    sred[y][x][0] = S1;  sred[y][x][1] = S2;
    sred[y][x][2] = A0;  sred[y][x][3] = A1;  sred[y][x][4] = A2;  sred[y][x][5] = AL;
    sred[y][x][6] = B0;  sred[y][x][7] = B1;  sred[y][x][8] = B2;  sred[y][x][9] = BL;
    __syncthreads();

    if (y == 0) {
#pragma unroll
        for (int yy = 1; yy < TY; ++yy) {
            S1 += sred[yy][x][0];  S2 += sred[yy][x][1];
            A0 += sred[yy][x][2];  A1 += sred[yy][x][3];
            A2 += sred[yy][x][4];  AL += sred[yy][x][5];
            B0 += sred[yy][x][6];  B1 += sred[yy][x][7];
            B2 += sred[yy][x][8];  BL += sred[yy][x][9];
        }
        // contribution of this pooled point (sum over all i,j pairs), fp64
        const double dAL = (double)AL - (double)BL;
        const double d0  = (double)A0 - (double)B0;
        const double d1  = (double)A1 - (double)B1;
        const double d2  = (double)A2 - (double)B2;
        scon[x] = (double)Bn * dAL
                - (0.5 * (double)S2 * d0 - (double)S1 * d1 + 0.5 * (double)Bn * d2);
    }
    __syncthreads();

    if (x == 0 && y == 0) {
        double s = 0.0;
#pragma unroll
        for (int j = 0; j < TX; ++j) s += scon[j];
        g_partials[blockIdx.x] = s;
    }
}

__global__ void gkl_reduce_kernel(float* __restrict__ out)
{
    __shared__ double s[NBLK];
    const int t = threadIdx.x;
    s[t] = g_partials[t];
    __syncthreads();
    for (int ofs = NBLK / 2; ofs > 0; ofs >>= 1) {
        if (t < ofs) s[t] += s[t + ofs];
        __syncthreads();
    }
    if (t == 0) out[0] = (float)(s[0] / ((double)Bn * (double)Bn));
}

extern "C" void kernel_launch(void* const* d_in, const int* in_sizes, int n_in,
                              void* d_out, int out_size)
{
    (void)in_sizes; (void)n_in; (void)out_size;
    const float* mu_a = (const float*)d_in[0];
    const float* lv_a = (const float*)d_in[1];
    const float* mu_b = (const float*)d_in[2];
    const float* lv_b = (const float*)d_in[3];

    dim3 blk(TX, TY);
    gkl_main_kernel<<<NBLK, blk>>>(mu_a, lv_a, mu_b, lv_b);
    gkl_reduce_kernel<<<1, NBLK>>>((float*)d_out);
}